// round 7
// baseline (speedup 1.0000x reference)
#include <cuda_runtime.h>
#include <math.h>

#define NA     4096
#define CUTF   5.0f
#define CUT2   25.0f
#define MAGIC  12582912.0f   // 1.5*2^23 : (x+MAGIC)-MAGIC == rint-to-even(x), |x| < 2^22
#define NCMAX  1024
#define BBLK   16            // k_build blocks (16 x 256 = 4096 atoms)
#define CBLK   512           // k_count blocks (8 warps x 512 = 4096 rows)

// Scratch (no device allocation allowed). Zero-initialized at module load;
// mutated state is restored by the terminal blocks each call (replay-safe).
__device__ float    g_mat[18];        // [0..8] inv(box), [9..17] box (row-major)
__device__ int      g_nc[3];          // cells per dim
__device__ int      g_hist[NCMAX];    // cell histogram (zeroed after use)
__device__ int      g_cell[NA];       // per-atom cell id
__device__ int      g_cs[NCMAX + 1];  // cell start offsets
__device__ float4   g_spos[NA];       // cell-sorted (x,y,z, idx-bits)
__device__ int      g_cnt[NA];        // per-row hit counts
__device__ int      g_off[NA];        // per-row exclusive offsets
__device__ int      g_total;          // total pairs
__device__ int      g_tick1;          // k_build ticket (self-resetting)
__device__ int      g_tick2;          // k_count ticket (self-resetting)
__device__ unsigned g_mask[NA * 128]; // per-row hit bitmask, ABSOLUTE j indexing

__device__ __forceinline__ int cell1d(float x, float L, int nc) {
    int c = (int)((x / L) * (float)nc);
    if (c < 0) c = 0;
    if (c >= nc) c = nc - 1;
    return c;
}

// Diagonal-box minimum image, bit-matching reference op order (validated R2-R5).
__device__ __forceinline__ float pair_d2_diag(float dx, float dy, float dz,
                                              float i0, float i1, float i2,
                                              float L0, float L1, float L2,
                                              float& ox, float& oy, float& oz) {
    float rx = __fsub_rn(__fadd_rn(__fmul_rn(dx, i0), MAGIC), MAGIC);
    float ry = __fsub_rn(__fadd_rn(__fmul_rn(dy, i1), MAGIC), MAGIC);
    float rz = __fsub_rn(__fadd_rn(__fmul_rn(dz, i2), MAGIC), MAGIC);
    ox = __fsub_rn(dx, __fmul_rn(rx, L0));
    oy = __fsub_rn(dy, __fmul_rn(ry, L1));
    oz = __fsub_rn(dz, __fmul_rn(rz, L2));
    return __fadd_rn(__fadd_rn(__fmul_rn(ox, ox), __fmul_rn(oy, oy)), __fmul_rn(oz, oz));
}

// ---------------------------------------------------------------------------
// Cell build, parallel: 16 blocks bin atoms (global hist atomics); the last
// block (ticket) scans the histogram, re-zeroes it, scatters the cell-sorted
// float4 array, and resets its ticket.
// ---------------------------------------------------------------------------
__global__ void __launch_bounds__(256)
k_build(const float* __restrict__ pos, const float* __restrict__ box) {
    const int t   = threadIdx.x;
    const int gid = blockIdx.x * 256 + t;

    if (gid == 0) {   // 3x3 inverse via cofactors (same formula as R2-R5)
        float b[9];
#pragma unroll
        for (int i = 0; i < 9; i++) b[i] = box[i];
        float c00 =  (b[4]*b[8] - b[5]*b[7]);
        float c01 = -(b[3]*b[8] - b[5]*b[6]);
        float c02 =  (b[3]*b[7] - b[4]*b[6]);
        float det = b[0]*c00 + b[1]*c01 + b[2]*c02;
        g_mat[0] = __fdiv_rn(c00, det);
        g_mat[3] = __fdiv_rn(c01, det);
        g_mat[6] = __fdiv_rn(c02, det);
        g_mat[1] = __fdiv_rn(-(b[1]*b[8] - b[2]*b[7]), det);
        g_mat[4] = __fdiv_rn( (b[0]*b[8] - b[2]*b[6]), det);
        g_mat[7] = __fdiv_rn(-(b[0]*b[7] - b[1]*b[6]), det);
        g_mat[2] = __fdiv_rn( (b[1]*b[5] - b[2]*b[4]), det);
        g_mat[5] = __fdiv_rn(-(b[0]*b[5] - b[2]*b[3]), det);
        g_mat[8] = __fdiv_rn( (b[0]*b[4] - b[1]*b[3]), det);
#pragma unroll
        for (int i = 0; i < 9; i++) g_mat[9 + i] = b[i];
    }

    const float L0 = box[0], L1 = box[4], L2 = box[8];
    int ncx = (int)(L0 / CUTF); ncx = max(3, min(ncx, 10));
    int ncy = (int)(L1 / CUTF); ncy = max(3, min(ncy, 10));
    int ncz = (int)(L2 / CUTF); ncz = max(3, min(ncz, 10));
    const int ncells = ncx * ncy * ncz;
    if (gid == 0) { g_nc[0] = ncx; g_nc[1] = ncy; g_nc[2] = ncz; }

    if (gid < NA) {     // one atom per thread
        const int cx = cell1d(pos[3*gid+0], L0, ncx);
        const int cy = cell1d(pos[3*gid+1], L1, ncy);
        const int cz = cell1d(pos[3*gid+2], L2, ncz);
        const int c  = (cz * ncy + cy) * ncx + cx;
        g_cell[gid] = c;
        atomicAdd(&g_hist[c], 1);
    }
    __threadfence();
    __syncthreads();
    __shared__ int s_last;
    if (t == 0) s_last = (atomicAdd(&g_tick1, 1) == BBLK - 1);
    __syncthreads();
    if (!s_last) return;
    __threadfence();

    // ----- terminal block: scan(1024) + re-zero hist + scatter + reset -----
    __shared__ int sbase[NCMAX];
    __shared__ int sfill[NCMAX];
    __shared__ int wsum[8];
    const int lane = t & 31, w = t >> 5;

    int cv[4], s = 0;
#pragma unroll
    for (int k = 0; k < 4; k++) { cv[k] = g_hist[4 * t + k]; s += cv[k]; }
    int incl = s;
#pragma unroll
    for (int d = 1; d < 32; d <<= 1) {
        int u = __shfl_up_sync(0xffffffffu, incl, d);
        if (lane >= d) incl += u;
    }
    if (lane == 31) wsum[w] = incl;
    __syncthreads();
    int wbase = 0;
#pragma unroll
    for (int q = 0; q < 8; q++) wbase += (q < w) ? wsum[q] : 0;
    int run = wbase + incl - s;
#pragma unroll
    for (int k = 0; k < 4; k++) {
        sbase[4 * t + k] = run;
        g_cs[4 * t + k]  = run;
        run += cv[k];
        g_hist[4 * t + k] = 0;      // restore for next call
        sfill[4 * t + k]  = 0;
    }
    if (t == 255) g_cs[NCMAX] = NA;   // sentinel (>= any used index)
    __syncthreads();

    for (int a = t; a < NA; a += 256) {
        const int c = g_cell[a];
        const int dst = sbase[c] + atomicAdd(&sfill[c], 1);
        g_spos[dst] = make_float4(pos[3*a+0], pos[3*a+1], pos[3*a+2],
                                  __int_as_float(a));
    }
    if (t == 0) g_tick1 = 0;          // restore ticket for next call
}

// ---------------------------------------------------------------------------
// COUNT pass (warp per row, float4 candidates) + fused terminal scan.
// ---------------------------------------------------------------------------
__global__ void __launch_bounds__(256)
k_count(const float* __restrict__ pos, float* __restrict__ out, int n_idx) {
    __shared__ unsigned smask[8][128];
    __shared__ int s_last;
    const int w = threadIdx.x >> 5, lane = threadIdx.x & 31;
    const int i = blockIdx.x * 8 + w;

    const float i0 = g_mat[0], i1 = g_mat[4], i2 = g_mat[8];
    const float L0 = g_mat[9], L1 = g_mat[13], L2 = g_mat[17];
    const int ncx = g_nc[0], ncy = g_nc[1], ncz = g_nc[2];
    const float xi = pos[3*i], yi = pos[3*i+1], zi = pos[3*i+2];

#pragma unroll
    for (int q = 0; q < 4; q++) smask[w][q * 32 + lane] = 0u;
    __syncwarp();

    const int cx = cell1d(xi, L0, ncx);
    const int cy = cell1d(yi, L1, ncy);
    const int cz = cell1d(zi, L2, ncz);

    auto scan_seg = [&](int s, int e) {
        for (int k = s + lane; k < e; k += 32) {
            const float4 p = g_spos[k];
            const int jo = __float_as_int(p.w);
            float ox, oy, oz;
            const float d2 = pair_d2_diag(xi - p.x, yi - p.y, zi - p.z,
                                          i0, i1, i2, L0, L1, L2, ox, oy, oz);
            if (jo > i && d2 < CUT2)
                atomicOr(&smask[w][jo >> 5], 1u << (jo & 31));
        }
    };

    for (int dz = -1; dz <= 1; dz++) {
        int czz = cz + dz; czz += (czz < 0) ? ncz : 0; czz -= (czz >= ncz) ? ncz : 0;
        for (int dy = -1; dy <= 1; dy++) {
            int cyy = cy + dy; cyy += (cyy < 0) ? ncy : 0; cyy -= (cyy >= ncy) ? ncy : 0;
            const int rb = (czz * ncy + cyy) * ncx;
            if (cx > 0 && cx < ncx - 1) {
                scan_seg(g_cs[rb + cx - 1], g_cs[rb + cx + 2]);
            } else if (cx == 0) {
                scan_seg(g_cs[rb],           g_cs[rb + 2]);
                scan_seg(g_cs[rb + ncx - 1], g_cs[rb + ncx]);
            } else {
                scan_seg(g_cs[rb + ncx - 2], g_cs[rb + ncx]);
                scan_seg(g_cs[rb],           g_cs[rb + 1]);
            }
        }
    }
    __syncwarp();

    uint4 mv = make_uint4(smask[w][4*lane], smask[w][4*lane+1],
                          smask[w][4*lane+2], smask[w][4*lane+3]);
    ((uint4*)(g_mask + (size_t)i * 128))[lane] = mv;
    int c = __popc(mv.x) + __popc(mv.y) + __popc(mv.z) + __popc(mv.w);
    c = __reduce_add_sync(0xffffffffu, c);
    if (lane == 0) g_cnt[i] = c;

    // -------- fused terminal scan --------
    __syncthreads();
    __threadfence();
    if (threadIdx.x == 0)
        s_last = (atomicAdd(&g_tick2, 1) == CBLK - 1);
    __syncthreads();
    if (!s_last) return;
    __threadfence();

    __shared__ int wsum[8];
    const int t = threadIdx.x;
    int cv[16], s = 0;
#pragma unroll
    for (int k = 0; k < 16; k++) { cv[k] = g_cnt[16 * t + k]; s += cv[k]; }
    int incl = s;
#pragma unroll
    for (int d = 1; d < 32; d <<= 1) {
        int u = __shfl_up_sync(0xffffffffu, incl, d);
        if (lane >= d) incl += u;
    }
    if (lane == 31) wsum[w] = incl;
    __syncthreads();
    int wbase = 0;
#pragma unroll
    for (int q = 0; q < 8; q++) wbase += (q < w) ? wsum[q] : 0;
    int run = wbase + incl - s;
#pragma unroll
    for (int k = 0; k < 16; k++) { g_off[16 * t + k] = run; run += cv[k]; }
    if (t == 255) { g_total = run; out[n_idx] = (float)run; }
    if (t == 0) g_tick2 = 0;          // restore ticket for next call
}

// ---------------------------------------------------------------------------
// FILL pass: warp per row, uint4 mask load, one warp scan, serial emit.
// Contiguous tail padding folded in.
// ---------------------------------------------------------------------------
__global__ void __launch_bounds__(256)
k_fill(const float* __restrict__ pos, float* __restrict__ out, int P) {
    const int w = threadIdx.x >> 5, lane = threadIdx.x & 31;
    const int i = blockIdx.x * 8 + w;             // 512 blocks x 8 warps

    const float i0 = g_mat[0], i1 = g_mat[4], i2 = g_mat[8];
    const float L0 = g_mat[9], L1 = g_mat[13], L2 = g_mat[17];
    const float xi = pos[3*i], yi = pos[3*i+1], zi = pos[3*i+2];

    const uint4 mv = ((const uint4*)(g_mask + (size_t)i * 128))[lane];
    const int c = __popc(mv.x) + __popc(mv.y) + __popc(mv.z) + __popc(mv.w);
    int incl = c;
#pragma unroll
    for (int d = 1; d < 32; d <<= 1) {
        int u = __shfl_up_sync(0xffffffffu, incl, d);
        if (lane >= d) incl += u;
    }
    int idx = g_off[i] + incl - c;

    unsigned ws[4] = {mv.x, mv.y, mv.z, mv.w};
#pragma unroll
    for (int q = 0; q < 4; q++) {
        unsigned wv = ws[q];
        while (wv) {
            const int b = __ffs(wv) - 1; wv &= (wv - 1);
            const int j = 128 * lane + 32 * q + b;
            float ox, oy, oz;
            const float d2 = pair_d2_diag(xi - __ldg(pos + 3*j),
                                          yi - __ldg(pos + 3*j + 1),
                                          zi - __ldg(pos + 3*j + 2),
                                          i0, i1, i2, L0, L1, L2, ox, oy, oz);
            out[idx]             = (float)i;
            out[(size_t)P + idx] = (float)j;
            float* dp = out + (size_t)2 * P + 3 * (size_t)idx;
            dp[0] = ox; dp[1] = oy; dp[2] = oz;
            out[(size_t)5 * P + idx] = sqrtf(d2);
            idx++;
        }
    }

    // ---- contiguous tail padding ----
    const int total = g_total;
    const int tid   = blockIdx.x * blockDim.x + threadIdx.x;
    const int nthr  = gridDim.x * blockDim.x;
    const int tail  = P - total;
    for (int k = tid; k < tail; k += nthr) {
        out[total + k]             = -1.0f;
        out[(size_t)P + total + k] = -1.0f;
    }
    const int dtail = 3 * tail;
    float* dbase = out + (size_t)2 * P + 3 * (size_t)total;
    for (int k = tid; k < dtail; k += nthr) dbase[k] = 0.0f;
    for (int k = tid; k < tail; k += nthr)
        out[(size_t)5 * P + total + k] = 0.0f;
}

extern "C" void kernel_launch(void* const* d_in, const int* in_sizes, int n_in,
                              void* d_out, int out_size) {
    const float* pos = (const float*)d_in[0];   // [4096, 3] float32
    const float* box = (const float*)d_in[1];   // [3, 3]   float32
    float* out = (float*)d_out;
    const int P = (out_size - 1) / 6;           // MAX_NUM_PAIRS

    k_build<<<BBLK, 256>>>(pos, box);           // parallel bin + fused scan/scatter
    k_count<<<CBLK, 256>>>(pos, out, 6 * P);    // bitmasks + fused scan/n_pairs
    k_fill<<<512, 256>>>(pos, out, P);          // ordered fill + tail padding
}